// round 13
// baseline (speedup 1.0000x reference)
#include <cuda_runtime.h>
#include <cuda_fp16.h>
#include <cuda_bf16.h>
#include <math.h>

// Problem constants
#define B     256
#define V     100
#define C     40
#define E     128
#define H     100
#define G4    400      // 4*H
#define M_TOT 32768    // B*E

// ---------------- device scratch ----------------
__device__ int   g_last[B];                          // built via atomicMax (idempotent)
__device__ __align__(16) float g_xseq[B * V * E];    // A[32768][100]
__device__ __align__(16) float g_xpart[M_TOT * G4];  // x @ W_ih^T + biases
__device__ float g_trueh[B * E];

// ---------------- helpers ----------------
__device__ __forceinline__ unsigned f2tf32(float f) {
    unsigned r;
    asm("cvt.rna.tf32.f32 %0, %1;" : "=r"(r) : "f"(f));
    return r;
}
__device__ __forceinline__ void mma8(float* d, const unsigned* a,
                                     unsigned b0, unsigned b1) {
    asm("mma.sync.aligned.m16n8k8.row.col.f32.tf32.tf32.f32 "
        "{%0,%1,%2,%3},{%4,%5,%6,%7},{%8,%9},{%0,%1,%2,%3};"
        : "+f"(d[0]), "+f"(d[1]), "+f"(d[2]), "+f"(d[3])
        : "r"(a[0]), "r"(a[1]), "r"(a[2]), "r"(a[3]), "r"(b0), "r"(b1));
}
// fp16 mma m16n8k16, f32 accumulate
__device__ __forceinline__ void mma16816(float* d, const unsigned* a,
                                         unsigned b0, unsigned b1) {
    asm("mma.sync.aligned.m16n8k16.row.col.f32.f16.f16.f32 "
        "{%0,%1,%2,%3},{%4,%5,%6,%7},{%8,%9},{%0,%1,%2,%3};"
        : "+f"(d[0]), "+f"(d[1]), "+f"(d[2]), "+f"(d[3])
        : "r"(a[0]), "r"(a[1]), "r"(a[2]), "r"(a[3]), "r"(b0), "r"(b1));
}
__device__ __forceinline__ float tanhapx(float x) {
    float r;
    asm("tanh.approx.f32 %0, %1;" : "=f"(r) : "f"(x));
    return r;
}
__device__ __forceinline__ float sigt(float x) {
    return fmaf(0.5f, tanhapx(0.5f * x), 0.5f);
}

// ---------------- K1: masked embedding sum + fused last-visit ----------
__global__ void k_embed(const int* __restrict__ diag,
                        const float* __restrict__ mask,
                        const float* __restrict__ table) {
    int flag = 0;
    if (threadIdx.x < 64) flag = diag[2 * threadIdx.x + 1];
    int is64 = __syncthreads_or(flag != 0) ? 0 : 1;

    int p    = blockIdx.x * 8 + (threadIdx.x >> 5);   // (b*V + v)
    int lane = threadIdx.x & 31;
    int b    = p / V;
    int v    = p - b * V;
    const float4* tab4 = (const float4*)table;
    float4 acc = make_float4(0.f, 0.f, 0.f, 0.f);
    bool has = false;
    int base = p * C;
    #pragma unroll
    for (int c4 = 0; c4 < C / 4; c4++) {
        float4 m4 = *(const float4*)(mask + base + c4 * 4);
        int code[4];
        #pragma unroll
        for (int q = 0; q < 4; q++)
            code[q] = diag[(base + c4 * 4 + q) << is64];
        float mm[4] = {m4.x, m4.y, m4.z, m4.w};
        #pragma unroll
        for (int q = 0; q < 4; q++) {
            has |= (mm[q] != 0.f);
            float4 t = tab4[code[q] * 32 + lane];
            acc.x += t.x * mm[q]; acc.y += t.y * mm[q];
            acc.z += t.z * mm[q]; acc.w += t.w * mm[q];
        }
    }
    ((float4*)g_xseq)[p * 32 + lane] = acc;
    if (lane == 0 && has) atomicMax(&g_last[b], v);
}

// ---------------- K2: single-TF32 tensor GEMM ----------------
#define BMg 128
#define BNg 80
#define SST 36

__global__ void __launch_bounds__(256, 2) k_gemm(const float* __restrict__ W,
                                                 const float* __restrict__ bih,
                                                 const float* __restrict__ bhh) {
    __shared__ unsigned As[BMg * SST];
    __shared__ unsigned Ws[BNg * SST];

    int tid = threadIdx.x;
    int wid = tid >> 5, lane = tid & 31;
    int wm = wid & 3, wn = wid >> 2;
    int g = lane >> 2, t = lane & 3;
    int m0 = blockIdx.x * BMg;
    int n0 = blockIdx.y * BNg;

    float d[2][5][4];
    #pragma unroll
    for (int ni = 0; ni < 5; ni++) {
        int cc = n0 + wn * 40 + ni * 8 + 2 * t;
        float b0 = bih[cc] + bhh[cc];
        float b1 = bih[cc + 1] + bhh[cc + 1];
        #pragma unroll
        for (int mi = 0; mi < 2; mi++) {
            d[mi][ni][0] = b0; d[mi][ni][1] = b1;
            d[mi][ni][2] = b0; d[mi][ni][3] = b1;
        }
    }

    #pragma unroll 1
    for (int kc = 0; kc < 4; kc++) {
        int k0 = kc * 32;
        #pragma unroll
        for (int i = 0; i < 16; i++) {
            int li = i * 256 + tid;
            int m = li >> 5, k = li & 31;
            float v = (k0 + k < 100) ? g_xseq[(m0 + m) * 100 + k0 + k] : 0.f;
            As[m * SST + k] = f2tf32(v);
        }
        #pragma unroll
        for (int i = 0; i < 10; i++) {
            int li = i * 256 + tid;
            int n = li >> 5, k = li & 31;
            float w = (k0 + k < 100) ? W[(n0 + n) * 100 + k0 + k] : 0.f;
            Ws[n * SST + k] = f2tf32(w);
        }
        __syncthreads();

        int ns = (kc == 3) ? 1 : 4;
        #pragma unroll
        for (int s = 0; s < 4; s++) {
            if (s >= ns) break;
            unsigned a[2][4];
            #pragma unroll
            for (int mi = 0; mi < 2; mi++) {
                int r = (wm * 32 + mi * 16 + g) * SST + s * 8 + t;
                a[mi][0] = As[r];
                a[mi][1] = As[r + 8 * SST];
                a[mi][2] = As[r + 4];
                a[mi][3] = As[r + 8 * SST + 4];
            }
            #pragma unroll
            for (int ni = 0; ni < 5; ni++) {
                int rb = (wn * 40 + ni * 8 + g) * SST + s * 8 + t;
                unsigned b0 = Ws[rb], b1 = Ws[rb + 4];
                #pragma unroll
                for (int mi = 0; mi < 2; mi++)
                    mma8(d[mi][ni], a[mi], b0, b1);
            }
        }
        __syncthreads();
    }

    #pragma unroll
    for (int mi = 0; mi < 2; mi++) {
        int r = m0 + wm * 32 + mi * 16 + g;
        #pragma unroll
        for (int ni = 0; ni < 5; ni++) {
            int cc = n0 + wn * 40 + ni * 8 + 2 * t;
            *(float2*)&g_xpart[r * G4 + cc]       = make_float2(d[mi][ni][0], d[mi][ni][1]);
            *(float2*)&g_xpart[(r + 8) * G4 + cc] = make_float2(d[mi][ni][2], d[mi][ni][3]);
        }
    }
}

// ---------------- K3: HMMA recurrence, 8 e-rows per CTA ------------------
// 16 CTAs, 256 thr (8 warps). gates[400x8] = W_hh[400x100] @ h[100x8] + x.
// M = 25 m16-tiles (warp w: tiles w*3..; warp 7 has 4). K padded to 112.
// W_hh held in A fragments (registers) for all 256 steps. h in smem fp16
// [row][k] stride 120 (conflict-free B-frag loads). Cell phase: 800 (u,r)
// pairs over 256 threads with register-prefetched x.
#define HB_STR 120
#define GS_STR 10

__global__ void __launch_bounds__(256, 1) k_rec(const float* __restrict__ Whh) {
    __shared__ float  gs[G4 * GS_STR];        // gate dots [m][r], 16KB
    __shared__ __half hB[8 * HB_STR];         // h [r][k(0..111 pad)], 1.9KB
    __shared__ int    last_s[B];

    int tid = threadIdx.x;
    int w   = tid >> 5, l = tid & 31;
    int g   = l >> 2, t4 = l & 3;
    int e0  = blockIdx.x * 8;
    int ntiles = (w == 7) ? 4 : 3;

    // ---- one-time: W_hh -> A fragments (fp16) ----
    unsigned Af[4][7][4];
    #pragma unroll
    for (int it = 0; it < 4; it++) {
        int mt = w * 3 + it;
        bool tv = (it < ntiles);
        #pragma unroll
        for (int kt = 0; kt < 7; kt++) {
            #pragma unroll
            for (int j = 0; j < 4; j++) {
                int m = mt * 16 + g + (j & 1) * 8;
                int k = kt * 16 + 2 * t4 + (j >> 1) * 8;
                float lo = 0.f, hi = 0.f;
                if (tv && k < 100)     lo = Whh[m * 100 + k];
                if (tv && k + 1 < 100) hi = Whh[m * 100 + k + 1];
                __half2 hv = __floats2half2_rn(lo, hi);
                Af[it][kt][j] = *(unsigned*)&hv;
            }
        }
    }

    // ---- pair assignment: P = tid + 256*i, u = P%100, r = P/100 ----
    int np = (tid < 32) ? 4 : 3;
    int pu[4], pr[4];
    #pragma unroll
    for (int i = 0; i < 4; i++) {
        int P = tid + 256 * i;
        if (P >= 800) P = 799;               // unused (np guard), keep in range
        pu[i] = P % 100;
        pr[i] = P / 100;
    }

    // init smem
    for (int i = tid; i < B; i += 256) last_s[i] = g_last[i];
    for (int i = tid; i < 8 * HB_STR / 2; i += 256)
        ((unsigned*)hB)[i] = 0u;
    float cst[4] = {0.f, 0.f, 0.f, 0.f};

    // initial x prefetch (t=0)
    float xr[4][4];
    #pragma unroll
    for (int i = 0; i < 4; i++) {
        #pragma unroll
        for (int cI = 0; cI < 4; cI++)
            xr[i][cI] = __ldg(&g_xpart[(e0 + pr[i]) * G4 + cI * H + pu[i]]);
    }
    __syncthreads();

    #pragma unroll 1
    for (int t = 0; t < B; t++) {
        // ---- mma phase: D = W_hh @ h ----
        float D[4][4];
        #pragma unroll
        for (int it = 0; it < 4; it++)
            #pragma unroll
            for (int j = 0; j < 4; j++) D[it][j] = 0.f;

        #pragma unroll
        for (int kt = 0; kt < 7; kt++) {
            int k0 = kt * 16;
            unsigned b0 = *(unsigned*)&hB[g * HB_STR + k0 + 2 * t4];
            unsigned b1 = *(unsigned*)&hB[g * HB_STR + k0 + 2 * t4 + 8];
            #pragma unroll
            for (int it = 0; it < 4; it++)
                if (it < ntiles)
                    mma16816(D[it], Af[it][kt], b0, b1);
        }

        // ---- store D -> gs[m][r] ----
        #pragma unroll
        for (int it = 0; it < 4; it++)
            if (it < ntiles) {
                int m = (w * 3 + it) * 16 + g;
                *(float2*)&gs[m * GS_STR + 2 * t4]       = make_float2(D[it][0], D[it][1]);
                *(float2*)&gs[(m + 8) * GS_STR + 2 * t4] = make_float2(D[it][2], D[it][3]);
            }
        __syncthreads();

        // ---- cell phase ----
        int lastu = last_s[t];
        int tn = (t + 1 < B) ? (t + 1) : (B - 1);
        #pragma unroll
        for (int i = 0; i < 4; i++) {
            if (i < np) {
                int u = pu[i], r = pr[i];
                float i_ = sigt(gs[u * GS_STR + r]             + xr[i][0]);
                float f_ = sigt(gs[(H + u) * GS_STR + r]       + xr[i][1]);
                float g_ = tanhapx(gs[(2 * H + u) * GS_STR + r] + xr[i][2]);
                float o_ = sigt(gs[(3 * H + u) * GS_STR + r]   + xr[i][3]);
                cst[i] = f_ * cst[i] + i_ * g_;
                float hv = o_ * tanhapx(cst[i]);
                hB[r * HB_STR + u] = __float2half_rn(hv);
                if (u == lastu) g_trueh[t * E + e0 + r] = hv;
                // prefetch next step's x
                const float* xb = &g_xpart[(tn * E + e0 + r) * G4 + u];
                xr[i][0] = __ldg(xb);
                xr[i][1] = __ldg(xb + H);
                xr[i][2] = __ldg(xb + 2 * H);
                xr[i][3] = __ldg(xb + 3 * H);
            }
        }
        __syncthreads();
    }
}

// ---------------- K4: final FC + sigmoid ----------------
__global__ void k_fc(const float* __restrict__ fcw,
                     const float* __restrict__ fcb,
                     float* __restrict__ out) {
    int warp = (blockIdx.x * blockDim.x + threadIdx.x) >> 5;
    int lane = threadIdx.x & 31;
    if (warp >= B) return;
    const float* th = g_trueh + warp * E;
    float acc = 0.f;
    #pragma unroll
    for (int k = 0; k < 4; k++) acc += th[lane + 32 * k] * fcw[lane + 32 * k];
    #pragma unroll
    for (int s = 16; s > 0; s >>= 1) acc += __shfl_down_sync(0xFFFFFFFFu, acc, s);
    if (lane == 0) out[warp] = sigt(acc + fcb[0]);
}

// ---------------- launcher: kernel launches ONLY ----------------
extern "C" void kernel_launch(void* const* d_in, const int* in_sizes, int n_in,
                              void* d_out, int out_size) {
    const int*   diag = (const int*)d_in[0];
    const float* mask = (const float*)d_in[1];
    const float* tab  = (const float*)d_in[2];
    const float* Wih  = (const float*)d_in[3];
    const float* Whh  = (const float*)d_in[4];
    const float* bih  = (const float*)d_in[5];
    const float* bhh  = (const float*)d_in[6];
    const float* fcw  = (const float*)d_in[7];
    const float* fcb  = (const float*)d_in[8];
    float* out = (float*)d_out;

    (void)in_sizes; (void)n_in; (void)out_size;

    k_embed<<<(B * V) / 8, 256>>>(diag, mask, tab);
    k_gemm<<<dim3(M_TOT / BMg, G4 / BNg), 256>>>(Wih, bih, bhh);
    k_rec<<<E / 8, 256>>>(Whh);
    k_fc<<<32, 256>>>(fcw, fcb, out);
}

// round 15
// speedup vs baseline: 1.3670x; 1.3670x over previous
#include <cuda_runtime.h>
#include <cuda_fp16.h>
#include <cuda_bf16.h>
#include <math.h>

// Problem constants
#define B     256
#define V     100
#define C     40
#define E     128
#define H     100
#define G4    400      // 4*H
#define M_TOT 32768    // B*E

// ---------------- device scratch ----------------
__device__ int   g_last[B];                          // built via atomicMax (idempotent)
__device__ __align__(16) float g_xseq[B * V * E];    // A[32768][100]
__device__ __align__(16) float g_xpart[M_TOT * G4];  // x @ W_ih^T + biases
__device__ float g_trueh[B * E];

// ---------------- helpers ----------------
__device__ __forceinline__ unsigned f2tf32(float f) {
    unsigned r;
    asm("cvt.rna.tf32.f32 %0, %1;" : "=r"(r) : "f"(f));
    return r;
}
__device__ __forceinline__ void mma8(float* d, const unsigned* a,
                                     unsigned b0, unsigned b1) {
    asm("mma.sync.aligned.m16n8k8.row.col.f32.tf32.tf32.f32 "
        "{%0,%1,%2,%3},{%4,%5,%6,%7},{%8,%9},{%0,%1,%2,%3};"
        : "+f"(d[0]), "+f"(d[1]), "+f"(d[2]), "+f"(d[3])
        : "r"(a[0]), "r"(a[1]), "r"(a[2]), "r"(a[3]), "r"(b0), "r"(b1));
}
// fp16 mma m16n8k16, f32 accumulate (verified on this toolchain in R13)
__device__ __forceinline__ void mma16816(float* d, const unsigned* a,
                                         unsigned b0, unsigned b1) {
    asm("mma.sync.aligned.m16n8k16.row.col.f32.f16.f16.f32 "
        "{%0,%1,%2,%3},{%4,%5,%6,%7},{%8,%9},{%0,%1,%2,%3};"
        : "+f"(d[0]), "+f"(d[1]), "+f"(d[2]), "+f"(d[3])
        : "r"(a[0]), "r"(a[1]), "r"(a[2]), "r"(a[3]), "r"(b0), "r"(b1));
}
__device__ __forceinline__ float tanhapx(float x) {
    float r;
    asm("tanh.approx.f32 %0, %1;" : "=f"(r) : "f"(x));
    return r;
}
__device__ __forceinline__ float sigt(float x) {
    return fmaf(0.5f, tanhapx(0.5f * x), 0.5f);
}

// ---------------- K1: masked embedding sum + fused last-visit ----------
__global__ void k_embed(const int* __restrict__ diag,
                        const float* __restrict__ mask,
                        const float* __restrict__ table) {
    int flag = 0;
    if (threadIdx.x < 64) flag = diag[2 * threadIdx.x + 1];
    int is64 = __syncthreads_or(flag != 0) ? 0 : 1;

    int p    = blockIdx.x * 8 + (threadIdx.x >> 5);   // (b*V + v)
    int lane = threadIdx.x & 31;
    int b    = p / V;
    int v    = p - b * V;
    const float4* tab4 = (const float4*)table;
    float4 acc = make_float4(0.f, 0.f, 0.f, 0.f);
    bool has = false;
    int base = p * C;
    #pragma unroll
    for (int c4 = 0; c4 < C / 4; c4++) {
        float4 m4 = *(const float4*)(mask + base + c4 * 4);
        int code[4];
        #pragma unroll
        for (int q = 0; q < 4; q++)
            code[q] = diag[(base + c4 * 4 + q) << is64];
        float mm[4] = {m4.x, m4.y, m4.z, m4.w};
        #pragma unroll
        for (int q = 0; q < 4; q++) {
            has |= (mm[q] != 0.f);
            float4 t = tab4[code[q] * 32 + lane];
            acc.x += t.x * mm[q]; acc.y += t.y * mm[q];
            acc.z += t.z * mm[q]; acc.w += t.w * mm[q];
        }
    }
    ((float4*)g_xseq)[p * 32 + lane] = acc;
    if (lane == 0 && has) atomicMax(&g_last[b], v);
}

// ---------------- K2: single-TF32 tensor GEMM ----------------
#define BMg 128
#define BNg 80
#define SST 36

__global__ void __launch_bounds__(256, 2) k_gemm(const float* __restrict__ W,
                                                 const float* __restrict__ bih,
                                                 const float* __restrict__ bhh) {
    __shared__ unsigned As[BMg * SST];
    __shared__ unsigned Ws[BNg * SST];

    int tid = threadIdx.x;
    int wid = tid >> 5, lane = tid & 31;
    int wm = wid & 3, wn = wid >> 2;
    int g = lane >> 2, t = lane & 3;
    int m0 = blockIdx.x * BMg;
    int n0 = blockIdx.y * BNg;

    float d[2][5][4];
    #pragma unroll
    for (int ni = 0; ni < 5; ni++) {
        int cc = n0 + wn * 40 + ni * 8 + 2 * t;
        float b0 = bih[cc] + bhh[cc];
        float b1 = bih[cc + 1] + bhh[cc + 1];
        #pragma unroll
        for (int mi = 0; mi < 2; mi++) {
            d[mi][ni][0] = b0; d[mi][ni][1] = b1;
            d[mi][ni][2] = b0; d[mi][ni][3] = b1;
        }
    }

    #pragma unroll 1
    for (int kc = 0; kc < 4; kc++) {
        int k0 = kc * 32;
        #pragma unroll
        for (int i = 0; i < 16; i++) {
            int li = i * 256 + tid;
            int m = li >> 5, k = li & 31;
            float v = (k0 + k < 100) ? g_xseq[(m0 + m) * 100 + k0 + k] : 0.f;
            As[m * SST + k] = f2tf32(v);
        }
        #pragma unroll
        for (int i = 0; i < 10; i++) {
            int li = i * 256 + tid;
            int n = li >> 5, k = li & 31;
            float w = (k0 + k < 100) ? W[(n0 + n) * 100 + k0 + k] : 0.f;
            Ws[n * SST + k] = f2tf32(w);
        }
        __syncthreads();

        int ns = (kc == 3) ? 1 : 4;
        #pragma unroll
        for (int s = 0; s < 4; s++) {
            if (s >= ns) break;
            unsigned a[2][4];
            #pragma unroll
            for (int mi = 0; mi < 2; mi++) {
                int r = (wm * 32 + mi * 16 + g) * SST + s * 8 + t;
                a[mi][0] = As[r];
                a[mi][1] = As[r + 8 * SST];
                a[mi][2] = As[r + 4];
                a[mi][3] = As[r + 8 * SST + 4];
            }
            #pragma unroll
            for (int ni = 0; ni < 5; ni++) {
                int rb = (wn * 40 + ni * 8 + g) * SST + s * 8 + t;
                unsigned b0 = Ws[rb], b1 = Ws[rb + 4];
                #pragma unroll
                for (int mi = 0; mi < 2; mi++)
                    mma8(d[mi][ni], a[mi], b0, b1);
            }
        }
        __syncthreads();
    }

    #pragma unroll
    for (int mi = 0; mi < 2; mi++) {
        int r = m0 + wm * 32 + mi * 16 + g;
        #pragma unroll
        for (int ni = 0; ni < 5; ni++) {
            int cc = n0 + wn * 40 + ni * 8 + 2 * t;
            *(float2*)&g_xpart[r * G4 + cc]       = make_float2(d[mi][ni][0], d[mi][ni][1]);
            *(float2*)&g_xpart[(r + 8) * G4 + cc] = make_float2(d[mi][ni][2], d[mi][ni][3]);
        }
    }
}

// ---------------- K3: HMMA recurrence, ONE e-row per CTA -----------------
// 128 CTAs x 256 thr (8 warps). gates[400] = W_hh[400x100] @ h[100] + x.
// M = 25 m16-tiles: warp w owns tiles w*3.. (warp 7 owns 4). K padded 112.
// W_hh held in A fragments (112 regs) for all 256 steps. h fp16 in row 0
// of hB[8][120] (rows 1..7 zero). Fragment conventions verified in R13.
#define HB_STR 120

__global__ void __launch_bounds__(256, 1) k_rec(const float* __restrict__ Whh) {
    __shared__ float  gs[G4];            // gate dots (n=0 column)
    __shared__ __half hB[8 * HB_STR];    // B tile [n-row][k], only row 0 live
    __shared__ int    last_s[B];

    int tid = threadIdx.x;
    int w   = tid >> 5, l = tid & 31;
    int g   = l >> 2, t4 = l & 3;
    int e   = blockIdx.x;
    int ntiles = (w == 7) ? 4 : 3;

    // ---- one-time: W_hh -> A fragments (fp16), verified layout ----
    unsigned Af[4][7][4];
    #pragma unroll
    for (int it = 0; it < 4; it++) {
        int mt = w * 3 + it;
        bool tv = (it < ntiles);
        #pragma unroll
        for (int kt = 0; kt < 7; kt++) {
            #pragma unroll
            for (int j = 0; j < 4; j++) {
                int m = mt * 16 + g + (j & 1) * 8;
                int k = kt * 16 + 2 * t4 + (j >> 1) * 8;
                float lo = 0.f, hi = 0.f;
                if (tv && k < 100)     lo = Whh[m * 100 + k];
                if (tv && k + 1 < 100) hi = Whh[m * 100 + k + 1];
                __half2 hv = __floats2half2_rn(lo, hi);
                Af[it][kt][j] = *(unsigned*)&hv;
            }
        }
    }

    for (int i = tid; i < B; i += 256) last_s[i] = g_last[i];
    for (int i = tid; i < 8 * HB_STR / 2; i += 256)
        ((unsigned*)hB)[i] = 0u;
    float c = 0.f;

    // x prefetch t=0 (threads 0..99)
    float xr0 = 0.f, xr1 = 0.f, xr2 = 0.f, xr3 = 0.f;
    if (tid < H) {
        const float* xb = &g_xpart[e * G4 + tid];
        xr0 = __ldg(xb); xr1 = __ldg(xb + H);
        xr2 = __ldg(xb + 2 * H); xr3 = __ldg(xb + 3 * H);
    }
    __syncthreads();

    #pragma unroll 1
    for (int t = 0; t < B; t++) {
        // ---- mma phase: D = W_hh @ h (only n=0 column meaningful) ----
        float D[4][4];
        #pragma unroll
        for (int it = 0; it < 4; it++)
            #pragma unroll
            for (int j = 0; j < 4; j++) D[it][j] = 0.f;

        #pragma unroll
        for (int kt = 0; kt < 7; kt++) {
            int k0 = kt * 16;
            unsigned b0 = *(unsigned*)&hB[g * HB_STR + k0 + 2 * t4];
            unsigned b1 = *(unsigned*)&hB[g * HB_STR + k0 + 2 * t4 + 8];
            #pragma unroll
            for (int it = 0; it < 4; it++)
                if (it < ntiles)
                    mma16816(D[it], Af[it][kt], b0, b1);
        }

        // n=0 column lives in t4==0 lanes: c0 = D[m][0], c2 = D[m+8][0]
        if (t4 == 0) {
            #pragma unroll
            for (int it = 0; it < 4; it++)
                if (it < ntiles) {
                    int m = (w * 3 + it) * 16 + g;
                    gs[m]     = D[it][0];
                    gs[m + 8] = D[it][2];
                }
        }
        __syncthreads();

        // ---- cell phase (threads 0..99) ----
        if (tid < H) {
            float iv = sigt(gs[tid] + xr0);
            float fv = sigt(gs[H + tid] + xr1);
            float gv = tanhapx(gs[2 * H + tid] + xr2);
            float ov = sigt(gs[3 * H + tid] + xr3);
            c = fv * c + iv * gv;
            float hv = ov * tanhapx(c);
            hB[tid] = __float2half_rn(hv);          // row 0 of B tile
            if (tid == last_s[t]) g_trueh[t * E + e] = hv;
            int tn = (t + 1 < B) ? (t + 1) : (B - 1);
            const float* xb = &g_xpart[(tn * E + e) * G4 + tid];
            xr0 = __ldg(xb); xr1 = __ldg(xb + H);
            xr2 = __ldg(xb + 2 * H); xr3 = __ldg(xb + 3 * H);
        }
        __syncthreads();
    }
}

// ---------------- K4: final FC + sigmoid ----------------
__global__ void k_fc(const float* __restrict__ fcw,
                     const float* __restrict__ fcb,
                     float* __restrict__ out) {
    int warp = (blockIdx.x * blockDim.x + threadIdx.x) >> 5;
    int lane = threadIdx.x & 31;
    if (warp >= B) return;
    const float* th = g_trueh + warp * E;
    float acc = 0.f;
    #pragma unroll
    for (int k = 0; k < 4; k++) acc += th[lane + 32 * k] * fcw[lane + 32 * k];
    #pragma unroll
    for (int s = 16; s > 0; s >>= 1) acc += __shfl_down_sync(0xFFFFFFFFu, acc, s);
    if (lane == 0) out[warp] = sigt(acc + fcb[0]);
}

// ---------------- launcher: kernel launches ONLY ----------------
extern "C" void kernel_launch(void* const* d_in, const int* in_sizes, int n_in,
                              void* d_out, int out_size) {
    const int*   diag = (const int*)d_in[0];
    const float* mask = (const float*)d_in[1];
    const float* tab  = (const float*)d_in[2];
    const float* Wih  = (const float*)d_in[3];
    const float* Whh  = (const float*)d_in[4];
    const float* bih  = (const float*)d_in[5];
    const float* bhh  = (const float*)d_in[6];
    const float* fcw  = (const float*)d_in[7];
    const float* fcb  = (const float*)d_in[8];
    float* out = (float*)d_out;

    (void)in_sizes; (void)n_in; (void)out_size;

    k_embed<<<(B * V) / 8, 256>>>(diag, mask, tab);
    k_gemm<<<dim3(M_TOT / BMg, G4 / BNg), 256>>>(Wih, bih, bhh);
    k_rec<<<E, 256>>>(Whh);
    k_fc<<<32, 256>>>(fcw, fcb, out);
}